// round 12
// baseline (speedup 1.0000x reference)
#include <cuda_runtime.h>
#include <math.h>

#define T_LEN 131072
#define NL 27
#define SD 512
#define QD 256
#define KC (NL*32)   // 864

typedef unsigned long long u64;

// ---------------- device scratch (no allocations allowed) ----------------
__device__ float g_x0[32*(size_t)T_LEN];       // residual ping
__device__ float g_x1[32*(size_t)T_LEN];       // residual pong
__device__ float g_G [(size_t)KC*T_LEN];       // all gate outputs [864][T]
__device__ float g_h [(size_t)SD*T_LEN];       // relu(Wall@G + c0)
__device__ float g_Wall[SD*KC];                // folded Wp1 @ Wskip_i
__device__ float g_c0[SD];
__device__ float g_bsum[SD];

// ---------------- f32x2 helpers ----------------
__device__ __forceinline__ u64 pk2(float x){ u64 r; asm("mov.b64 %0,{%1,%1};":"=l"(r):"f"(x)); return r; }
__device__ __forceinline__ void fma2(u64 &d, u64 a, u64 b){ asm("fma.rn.f32x2 %0,%1,%2,%0;":"+l"(d):"l"(a),"l"(b)); }
__device__ __forceinline__ u64 add2(u64 a, u64 b){ u64 r; asm("add.rn.f32x2 %0,%1,%2;":"=l"(r):"l"(a),"l"(b)); return r; }
__device__ __forceinline__ void unpk(u64 v, float &a, float &b){ asm("mov.b64 {%0,%1},%2;":"=f"(a),"=f"(b):"l"(v)); }

// ---------------- initial conv: [1,T] -> [32,T], k=3, pad=1 ----------------
__global__ void k_conv0(const float* __restrict__ x, const float* __restrict__ Wc,
                        const float* __restrict__ bc){
    __shared__ float4 w[32];
    int tid = threadIdx.x;
    if (tid < 32) w[tid] = make_float4(Wc[tid*3], Wc[tid*3+1], Wc[tid*3+2], bc[tid]);
    __syncthreads();
    int t = blockIdx.x*256 + tid;
    float xm = (t > 0)        ? x[t-1] : 0.f;
    float x0 = x[t];
    float xp = (t < T_LEN-1)  ? x[t+1] : 0.f;
#pragma unroll
    for (int o = 0; o < 32; o++){
        float4 q = w[o];
        g_x0[(size_t)o*T_LEN + t] = q.w + q.x*xm + q.y*x0 + q.z*xp;
    }
}

// ---------------- bsum[m] = sum_i bskip[i][m] ----------------
__global__ void k_bsum(const float* __restrict__ bskip){
    int m = blockIdx.x*256 + threadIdx.x;
    if (m < SD){
        float s = 0.f;
        for (int i = 0; i < NL; i++) s += bskip[i*SD + m];
        g_bsum[m] = s;
    }
}

// ---------------- c0[s] = bp1[s] + sum_m Wp1[s][m]*bsum[m] ----------------
__global__ void k_c0(const float* __restrict__ Wp1, const float* __restrict__ bp1){
    __shared__ float red[128];
    int s = blockIdx.x, tid = threadIdx.x;
    float acc = 0.f;
    for (int m = tid; m < SD; m += 128) acc += Wp1[s*SD + m]*g_bsum[m];
    red[tid] = acc; __syncthreads();
    for (int st = 64; st > 0; st >>= 1){
        if (tid < st) red[tid] += red[tid+st];
        __syncthreads();
    }
    if (tid == 0) g_c0[s] = red[0] + bp1[s];
}

// ---------------- Wall[s][i*32+c] = sum_m Wp1[s][m]*Wskip[i][m][c] ----------------
__global__ void k_fold(const float* __restrict__ Wp1, const float* __restrict__ Wsk){
    __shared__ float wr[16*512];               // 16 rows of Wp1
    int s0 = blockIdx.x*16, tid = threadIdx.x; // 864 threads: tid = i*32+c
    for (int i = tid; i < 16*512; i += 864)
        wr[i] = Wp1[(size_t)(s0 + (i>>9))*SD + (i & 511)];
    __syncthreads();
    int i = tid >> 5, c = tid & 31;
    float acc[16];
#pragma unroll
    for (int u = 0; u < 16; u++) acc[u] = 0.f;
    const float* wp = Wsk + (size_t)i*SD*32 + c;
    for (int m = 0; m < SD; m++){
        float v = wp[m*32];
#pragma unroll
        for (int u = 0; u < 16; u++) acc[u] += wr[u*512 + m]*v;
    }
#pragma unroll
    for (int u = 0; u < 16; u++) g_Wall[(s0+u)*KC + tid] = acc[u];
}

// ---------------- one WaveNet layer ----------------
// smem floats: sWt 3072 | sWs 3072 | sWd 1024 | biases 96 | sxm/sx0/sxp 4096*3 | sg 4096
#define LSMEM_F (7264 + 16384)
__global__ void __launch_bounds__(256) k_layer(
    const float* __restrict__ Wt, const float* __restrict__ bt,
    const float* __restrict__ Ws, const float* __restrict__ bs,
    const float* __restrict__ Wd, const float* __restrict__ bd,
    int layer, int dil)
{
    extern __shared__ float sm[];
    float* sWt = sm;              // [c*3+k][o]  (o fastest -> conflict-free reads)
    float* sWs = sm + 3072;
    float* sWd = sm + 6144;       // [c][o]
    float* sbt = sm + 7168; float* sbs = sm + 7200; float* sbd = sm + 7232;
    float* sxm = sm + 7264;       // [c][128]
    float* sx0 = sm + 7264 + 4096;
    float* sxp = sm + 7264 + 8192;
    float* sg  = sm + 7264 + 12288;

    const float* xin  = (layer & 1) ? g_x1 : g_x0;
    float*       xout = (layer & 1) ? g_x0 : g_x1;

    int tid = threadIdx.x;
    int tb  = blockIdx.x*128;

    const float* Wtl = Wt + layer*3072;
    const float* Wsl = Ws + layer*3072;
    const float* Wdl = Wd + layer*1024;
    for (int i = tid; i < 3072; i += 256){
        int o = i/96, ck = i%96;
        sWt[ck*32 + o] = Wtl[i];
        sWs[ck*32 + o] = Wsl[i];
    }
    for (int i = tid; i < 1024; i += 256){
        int o = i >> 5, c = i & 31;
        sWd[c*32 + o] = Wdl[i];
    }
    if (tid < 32){ sbt[tid] = bt[layer*32+tid]; sbs[tid] = bs[layer*32+tid]; sbd[tid] = bd[layer*32+tid]; }
    for (int i = tid; i < 4096; i += 256){
        int c = i >> 7, tt = i & 127; int t = tb + tt;
        sx0[i] = xin[(size_t)c*T_LEN + t];
        int tm = t - dil; sxm[i] = (tm >= 0)    ? xin[(size_t)c*T_LEN + tm] : 0.f;
        int tp = t + dil; sxp[i] = (tp < T_LEN) ? xin[(size_t)c*T_LEN + tp] : 0.f;
    }
    __syncthreads();

    int o = tid >> 3, tq = tid & 7, t0 = tq*16;   // 1 output ch x 16 timesteps
    u64 a[8], b[8];
    {
        u64 ia = pk2(sbt[o]), ib = pk2(sbs[o]);
#pragma unroll
        for (int j = 0; j < 8; j++){ a[j] = ia; b[j] = ib; }
    }
#pragma unroll 2
    for (int c = 0; c < 32; c++){
        u64 wa0 = pk2(sWt[(c*3+0)*32+o]), wa1 = pk2(sWt[(c*3+1)*32+o]), wa2 = pk2(sWt[(c*3+2)*32+o]);
        u64 wb0 = pk2(sWs[(c*3+0)*32+o]), wb1 = pk2(sWs[(c*3+1)*32+o]), wb2 = pk2(sWs[(c*3+2)*32+o]);
        const u64* pm = (const u64*)&sxm[c*128 + t0];
        const u64* p0 = (const u64*)&sx0[c*128 + t0];
        const u64* pp = (const u64*)&sxp[c*128 + t0];
#pragma unroll
        for (int j = 0; j < 8; j++){
            fma2(a[j], wa0, pm[j]); fma2(a[j], wa1, p0[j]); fma2(a[j], wa2, pp[j]);
            fma2(b[j], wb0, pm[j]); fma2(b[j], wb1, p0[j]); fma2(b[j], wb2, pp[j]);
        }
    }
    // g = tanh(a)*sigmoid(b)
    float* dstS = &sg[o*128 + t0];
    float* dstG = &g_G[((size_t)layer*32 + o)*T_LEN + tb + t0];
#pragma unroll
    for (int j = 0; j < 8; j++){
        float av0, av1, bv0, bv1;
        unpk(a[j], av0, av1); unpk(b[j], bv0, bv1);
        float e0 = __expf(2.f*fminf(fmaxf(av0, -15.f), 15.f));
        float e1 = __expf(2.f*fminf(fmaxf(av1, -15.f), 15.f));
        float th0 = __fdividef(e0 - 1.f, e0 + 1.f);
        float th1 = __fdividef(e1 - 1.f, e1 + 1.f);
        float sg0 = __fdividef(1.f, 1.f + __expf(-bv0));
        float sg1 = __fdividef(1.f, 1.f + __expf(-bv1));
        float gv0 = th0*sg0, gv1 = th1*sg1;
        dstS[2*j] = gv0; dstS[2*j+1] = gv1;
        float2 gw; gw.x = gv0; gw.y = gv1;
        *(float2*)&dstG[2*j] = gw;
    }
    __syncthreads();

    // dense 1x1 + residual
    u64 r[8];
    {
        u64 ir = pk2(sbd[o]);
#pragma unroll
        for (int j = 0; j < 8; j++) r[j] = ir;
    }
#pragma unroll 4
    for (int c = 0; c < 32; c++){
        u64 w = pk2(sWd[c*32 + o]);
        const u64* pg = (const u64*)&sg[c*128 + t0];
#pragma unroll
        for (int j = 0; j < 8; j++) fma2(r[j], w, pg[j]);
    }
    const u64* px = (const u64*)&sx0[o*128 + t0];
    u64* dx = (u64*)&xout[(size_t)o*T_LEN + tb + t0];
#pragma unroll
    for (int j = 0; j < 8; j++) dx[j] = add2(r[j], px[j]);
}

// ---------------- GEMM: C[M][T] = (relu?)(A[M][K] @ B[K][T] + bias) ----------------
// block tile 64 rows x 128 cols, thread = 4 rows x 8 cols (f32x2 pairs)
__device__ __forceinline__ void gemm_body(const float* __restrict__ A, const float* __restrict__ B,
                                          const float* __restrict__ bias, float* __restrict__ C,
                                          int K, bool relu)
{
    __shared__ float As[32][68];   // [k][row], pad 68 -> conflict-free + aligned LDS.128
    __shared__ float Bs[32][128];
    int tid = threadIdx.x;
    int tb = blockIdx.x*128, m0 = blockIdx.y*64;
    int tx = tid & 15, ty = tid >> 4;
    int c0 = tx*8, r0 = ty*4;
    u64 acc[4][4];
#pragma unroll
    for (int i = 0; i < 4; i++)
#pragma unroll
        for (int j = 0; j < 4; j++) acc[i][j] = 0ull;

    for (int kc = 0; kc < K; kc += 32){
#pragma unroll
        for (int u = 0; u < 2; u++){           // A tile 64x32, transpose on store
            int fi = tid + u*256; int row = fi >> 3, kq = fi & 7;
            float4 v = *(const float4*)&A[(size_t)(m0+row)*K + kc + kq*4];
            As[kq*4+0][row] = v.x; As[kq*4+1][row] = v.y;
            As[kq*4+2][row] = v.z; As[kq*4+3][row] = v.w;
        }
#pragma unroll
        for (int u = 0; u < 4; u++){           // B tile 32x128
            int fi = tid + u*256; int kr = fi >> 5, cq = fi & 31;
            *(float4*)&Bs[kr][cq*4] = *(const float4*)&B[(size_t)(kc+kr)*T_LEN + tb + cq*4];
        }
        __syncthreads();
#pragma unroll 8
        for (int k = 0; k < 32; k++){
            float4 av = *(const float4*)&As[k][r0];
            u64 a0 = pk2(av.x), a1 = pk2(av.y), a2 = pk2(av.z), a3 = pk2(av.w);
            const u64* bv = (const u64*)&Bs[k][c0];
#pragma unroll
            for (int j = 0; j < 4; j++){
                u64 bb = bv[j];
                fma2(acc[0][j], a0, bb); fma2(acc[1][j], a1, bb);
                fma2(acc[2][j], a2, bb); fma2(acc[3][j], a3, bb);
            }
        }
        __syncthreads();
    }
#pragma unroll
    for (int i = 0; i < 4; i++){
        int row = m0 + r0 + i;
        float bv = bias[row];
        float* cp = &C[(size_t)row*T_LEN + tb + c0];
#pragma unroll
        for (int j = 0; j < 4; j++){
            float v0, v1; unpk(acc[i][j], v0, v1);
            v0 += bv; v1 += bv;
            if (relu){ v0 = fmaxf(v0, 0.f); v1 = fmaxf(v1, 0.f); }
            cp[2*j] = v0; cp[2*j+1] = v1;
        }
    }
}

__global__ void __launch_bounds__(256) k_gemm2(){          // h = relu(Wall@G + c0)
    gemm_body(g_Wall, g_G, g_c0, g_h, KC, true);
}
__global__ void __launch_bounds__(256) k_gemm3(const float* __restrict__ Wp2,
                                               const float* __restrict__ bp2,
                                               float* __restrict__ out){
    gemm_body(Wp2, g_h, bp2, out, SD, false);
}

// ---------------- in-place log_softmax over 256 channels ----------------
__global__ void k_lsm(float* __restrict__ out){
    int t = blockIdx.x*256 + threadIdx.x;
    float m = -1e30f;
#pragma unroll 8
    for (int q = 0; q < QD; q++) m = fmaxf(m, out[(size_t)q*T_LEN + t]);
    float s = 0.f;
#pragma unroll 8
    for (int q = 0; q < QD; q++) s += __expf(out[(size_t)q*T_LEN + t] - m);
    float lz = m + logf(s);
#pragma unroll 8
    for (int q = 0; q < QD; q++) out[(size_t)q*T_LEN + t] -= lz;
}

// ---------------- launch ----------------
extern "C" void kernel_launch(void* const* d_in, const int* in_sizes, int n_in,
                              void* d_out, int out_size){
    const float* x     = (const float*)d_in[0];
    const float* Wc    = (const float*)d_in[1];
    const float* bc    = (const float*)d_in[2];
    const float* Wt    = (const float*)d_in[3];
    const float* bt    = (const float*)d_in[4];
    const float* Ws    = (const float*)d_in[5];
    const float* bs    = (const float*)d_in[6];
    const float* Wskip = (const float*)d_in[7];
    const float* bskip = (const float*)d_in[8];
    const float* Wd    = (const float*)d_in[9];
    const float* bd    = (const float*)d_in[10];
    const float* Wp1   = (const float*)d_in[11];
    const float* bp1   = (const float*)d_in[12];
    const float* Wp2   = (const float*)d_in[13];
    const float* bp2   = (const float*)d_in[14];
    float* out = (float*)d_out;

    static const int DIL[NL] = {1,2,4,8,16,32,64,128,256,
                                1,2,4,8,16,32,64,128,256,
                                1,2,4,8,16,32,64,128,256};

    cudaFuncSetAttribute(k_layer, cudaFuncAttributeMaxDynamicSharedMemorySize, LSMEM_F*4);

    k_bsum<<<2, 256>>>(bskip);
    k_c0<<<SD, 128>>>(Wp1, bp1);
    k_fold<<<32, 864>>>(Wp1, Wskip);
    k_conv0<<<T_LEN/256, 256>>>(x, Wc, bc);
    for (int i = 0; i < NL; i++)
        k_layer<<<T_LEN/128, 256, LSMEM_F*4>>>(Wt, bt, Ws, bs, Wd, bd, i, DIL[i]);
    k_gemm2<<<dim3(T_LEN/128, SD/64), 256>>>();
    k_gemm3<<<dim3(T_LEN/128, QD/64), 256>>>(Wp2, bp2, out);
    k_lsm<<<T_LEN/256, 256>>>(out);
}

// round 15
// speedup vs baseline: 1.5340x; 1.5340x over previous
#include <cuda_runtime.h>
#include <cuda_bf16.h>
#include <math.h>
#include <stdint.h>

#define T_LEN 131072
#define NL 27
#define SD 512
#define QD 256
#define KC (NL*32)
#define KPAD 896

typedef unsigned long long u64;

__device__ float g_x0[32*(size_t)T_LEN];
__device__ float g_x1[32*(size_t)T_LEN];
__device__ __nv_bfloat16 g_Gt[(size_t)T_LEN*KPAD];
__device__ __nv_bfloat16 g_ht[(size_t)T_LEN*SD];
__device__ float g_Wall[SD*KC];
__device__ __nv_bfloat16 g_Wallb[SD*KPAD];
__device__ __nv_bfloat16 g_Wp2b[QD*SD];
__device__ float g_c0[SD];
__device__ float g_bsum[SD];

__device__ __forceinline__ u64 pk2(float x){ u64 r; asm("mov.b64 %0,{%1,%1};":"=l"(r):"f"(x)); return r; }
__device__ __forceinline__ void fma2(u64 &d, u64 a, u64 b){ asm("fma.rn.f32x2 %0,%1,%2,%0;":"+l"(d):"l"(a),"l"(b)); }
__device__ __forceinline__ u64 add2(u64 a, u64 b){ u64 r; asm("add.rn.f32x2 %0,%1,%2;":"=l"(r):"l"(a),"l"(b)); return r; }
__device__ __forceinline__ void unpk(u64 v, float &a, float &b){ asm("mov.b64 {%0,%1},%2;":"=f"(a),"=f"(b):"l"(v)); }

__device__ __forceinline__ uint32_t smem_u32(const void* p){
    uint32_t a; asm("{ .reg .u64 t; cvta.to.shared.u64 t, %1; cvt.u32.u64 %0, t; }":"=r"(a):"l"(p)); return a;
}
#define SW128(o) ((uint32_t)(o) ^ ((((uint32_t)(o))>>3)&0x70u))

__device__ __forceinline__ void ldsm4(uint32_t &r0,uint32_t &r1,uint32_t &r2,uint32_t &r3,uint32_t a){
    asm volatile("ldmatrix.sync.aligned.m8n8.x4.shared.b16 {%0,%1,%2,%3}, [%4];"
        : "=r"(r0),"=r"(r1),"=r"(r2),"=r"(r3) : "r"(a));
}
__device__ __forceinline__ void mma16816(float* c, const uint32_t* a, const uint32_t* b){
    asm volatile("mma.sync.aligned.m16n8k16.row.col.f32.bf16.bf16.f32 "
        "{%0,%1,%2,%3}, {%4,%5,%6,%7}, {%8,%9}, {%0,%1,%2,%3};"
        : "+f"(c[0]),"+f"(c[1]),"+f"(c[2]),"+f"(c[3])
        : "r"(a[0]),"r"(a[1]),"r"(a[2]),"r"(a[3]),"r"(b[0]),"r"(b[1]));
}

// ---------------- small kernels ----------------
__global__ void k_padG(){
    size_t t = blockIdx.x*256 + threadIdx.x;
    uint4 z = make_uint4(0,0,0,0);
    uint4* d = (uint4*)(g_Gt + t*KPAD + KC);
    d[0] = z; d[1] = z; d[2] = z; d[3] = z;
}
__global__ void k_conv0(const float* __restrict__ x, const float* __restrict__ Wc,
                        const float* __restrict__ bc){
    __shared__ float4 w[32];
    int tid = threadIdx.x;
    if (tid < 32) w[tid] = make_float4(Wc[tid*3], Wc[tid*3+1], Wc[tid*3+2], bc[tid]);
    __syncthreads();
    int t = blockIdx.x*256 + tid;
    float xm = (t > 0)       ? x[t-1] : 0.f;
    float x0 = x[t];
    float xp = (t < T_LEN-1) ? x[t+1] : 0.f;
#pragma unroll
    for (int o = 0; o < 32; o++){
        float4 q = w[o];
        g_x0[(size_t)o*T_LEN + t] = q.w + q.x*xm + q.y*x0 + q.z*xp;
    }
}
__global__ void k_bsum(const float* __restrict__ bskip){
    int m = blockIdx.x*256 + threadIdx.x;
    if (m < SD){
        float s = 0.f;
        for (int i = 0; i < NL; i++) s += bskip[i*SD + m];
        g_bsum[m] = s;
    }
}
__global__ void k_c0(const float* __restrict__ Wp1, const float* __restrict__ bp1){
    __shared__ float red[128];
    int s = blockIdx.x, tid = threadIdx.x;
    float acc = 0.f;
    for (int m = tid; m < SD; m += 128) acc += Wp1[s*SD + m]*g_bsum[m];
    red[tid] = acc; __syncthreads();
    for (int st = 64; st > 0; st >>= 1){
        if (tid < st) red[tid] += red[tid+st];
        __syncthreads();
    }
    if (tid == 0) g_c0[s] = red[0] + bp1[s];
}
__global__ void k_fold(const float* __restrict__ Wp1, const float* __restrict__ Wsk){
    __shared__ float wr[16*512];
    int s0 = blockIdx.x*16, tid = threadIdx.x;
    for (int i = tid; i < 16*512; i += 864)
        wr[i] = Wp1[(size_t)(s0 + (i>>9))*SD + (i & 511)];
    __syncthreads();
    int i = tid >> 5, c = tid & 31;
    float acc[16];
#pragma unroll
    for (int u = 0; u < 16; u++) acc[u] = 0.f;
    const float* wp = Wsk + (size_t)i*SD*32 + c;
    for (int m = 0; m < SD; m++){
        float v = wp[m*32];
#pragma unroll
        for (int u = 0; u < 16; u++) acc[u] += wr[u*512 + m]*v;
    }
#pragma unroll
    for (int u = 0; u < 16; u++) g_Wall[(s0+u)*KC + tid] = acc[u];
}
__global__ void k_cvtWall(){
    int row = blockIdx.x;
    for (int k = threadIdx.x; k < KPAD; k += 256)
        g_Wallb[row*KPAD + k] = __float2bfloat16(k < KC ? g_Wall[row*KC + k] : 0.f);
}
__global__ void k_cvtWp2(const float* __restrict__ Wp2){
    int row = blockIdx.x;
    for (int k = threadIdx.x; k < SD; k += 256)
        g_Wp2b[row*SD + k] = __float2bfloat16(Wp2[row*SD + k]);
}

// ---------------- WaveNet layer (unchanged compute; gates -> bf16 Gt) ----------------
#define LSMEM_F (7264 + 16384)
__global__ void __launch_bounds__(256) k_layer(
    const float* __restrict__ Wt, const float* __restrict__ bt,
    const float* __restrict__ Ws, const float* __restrict__ bs,
    const float* __restrict__ Wd, const float* __restrict__ bd,
    int layer, int dil)
{
    extern __shared__ float sm[];
    float* sWt = sm;
    float* sWs = sm + 3072;
    float* sWd = sm + 6144;
    float* sbt = sm + 7168; float* sbs = sm + 7200; float* sbd = sm + 7232;
    float* sxm = sm + 7264;
    float* sx0 = sm + 7264 + 4096;
    float* sxp = sm + 7264 + 8192;
    float* sg  = sm + 7264 + 12288;

    const float* xin  = (layer & 1) ? g_x1 : g_x0;
    float*       xout = (layer & 1) ? g_x0 : g_x1;
    int tid = threadIdx.x;
    int tb  = blockIdx.x*128;

    const float* Wtl = Wt + layer*3072;
    const float* Wsl = Ws + layer*3072;
    const float* Wdl = Wd + layer*1024;
    for (int i = tid; i < 3072; i += 256){
        int o = i/96, ck = i%96;
        sWt[ck*32 + o] = Wtl[i];
        sWs[ck*32 + o] = Wsl[i];
    }
    for (int i = tid; i < 1024; i += 256){
        int o = i >> 5, c = i & 31;
        sWd[c*32 + o] = Wdl[i];
    }
    if (tid < 32){ sbt[tid] = bt[layer*32+tid]; sbs[tid] = bs[layer*32+tid]; sbd[tid] = bd[layer*32+tid]; }
    for (int i = tid; i < 4096; i += 256){
        int c = i >> 7, tt = i & 127; int t = tb + tt;
        sx0[i] = xin[(size_t)c*T_LEN + t];
        int tm = t - dil; sxm[i] = (tm >= 0)    ? xin[(size_t)c*T_LEN + tm] : 0.f;
        int tp = t + dil; sxp[i] = (tp < T_LEN) ? xin[(size_t)c*T_LEN + tp] : 0.f;
    }
    __syncthreads();

    int o = tid >> 3, tq = tid & 7, t0 = tq*16;
    u64 a[8], b[8];
    {
        u64 ia = pk2(sbt[o]), ib = pk2(sbs[o]);
#pragma unroll
        for (int j = 0; j < 8; j++){ a[j] = ia; b[j] = ib; }
    }
#pragma unroll 2
    for (int c = 0; c < 32; c++){
        u64 wa0 = pk2(sWt[(c*3+0)*32+o]), wa1 = pk2(sWt[(c*3+1)*32+o]), wa2 = pk2(sWt[(c*3+2)*32+o]);
        u64 wb0 = pk2(sWs[(c*3+0)*32+o]), wb1 = pk2(sWs[(c*3+1)*32+o]), wb2 = pk2(sWs[(c*3+2)*32+o]);
        const u64* pm = (const u64*)&sxm[c*128 + t0];
        const u64* p0 = (const u64*)&sx0[c*128 + t0];
        const u64* pp = (const u64*)&sxp[c*128 + t0];
#pragma unroll
        for (int j = 0; j < 8; j++){
            fma2(a[j], wa0, pm[j]); fma2(a[j], wa1, p0[j]); fma2(a[j], wa2, pp[j]);
            fma2(b[j], wb0, pm[j]); fma2(b[j], wb1, p0[j]); fma2(b[j], wb2, pp[j]);
        }
    }
    float* dstS = &sg[o*128 + t0];
#pragma unroll
    for (int j = 0; j < 8; j++){
        float av0, av1, bv0, bv1;
        unpk(a[j], av0, av1); unpk(b[j], bv0, bv1);
        float e0 = __expf(2.f*fminf(fmaxf(av0, -15.f), 15.f));
        float e1 = __expf(2.f*fminf(fmaxf(av1, -15.f), 15.f));
        float th0 = __fdividef(e0 - 1.f, e0 + 1.f);
        float th1 = __fdividef(e1 - 1.f, e1 + 1.f);
        float sg0 = __fdividef(1.f, 1.f + __expf(-bv0));
        float sg1 = __fdividef(1.f, 1.f + __expf(-bv1));
        dstS[2*j]   = th0*sg0;
        dstS[2*j+1] = th1*sg1;
    }
    __syncthreads();

    u64 r[8];
    {
        u64 ir = pk2(sbd[o]);
#pragma unroll
        for (int j = 0; j < 8; j++) r[j] = ir;
    }
#pragma unroll 4
    for (int c = 0; c < 32; c++){
        u64 w = pk2(sWd[c*32 + o]);
        const u64* pg = (const u64*)&sg[c*128 + t0];
#pragma unroll
        for (int j = 0; j < 8; j++) fma2(r[j], w, pg[j]);
    }
    const u64* px = (const u64*)&sx0[o*128 + t0];
    u64* dx = (u64*)&xout[(size_t)o*T_LEN + tb + t0];
#pragma unroll
    for (int j = 0; j < 8; j++) dx[j] = add2(r[j], px[j]);

    // transposed bf16 gate store: Gt[t][layer*32 .. +32]
    {
        int tI = tid >> 1, half = tid & 1;
        uint32_t pk[8];
#pragma unroll
        for (int u = 0; u < 8; u++){
            float f0 = sg[(half*16 + 2*u    )*128 + tI];
            float f1 = sg[(half*16 + 2*u + 1)*128 + tI];
            __nv_bfloat162 bb = __floats2bfloat162_rn(f0, f1);
            pk[u] = *(uint32_t*)&bb;
        }
        uint4* dst = (uint4*)(g_Gt + (size_t)(tb + tI)*KPAD + layer*32 + half*16);
        dst[0] = make_uint4(pk[0],pk[1],pk[2],pk[3]);
        dst[1] = make_uint4(pk[4],pk[5],pk[6],pk[7]);
    }
}

// ---------------- HMMA GEMM2: ht = relu(Gt @ Wallb^T + c0), bf16 out ----------------
#define G2_SMEM 34816
__global__ void __launch_bounds__(256) k_hmma2(){
    extern __shared__ char smc[];
    __shared__ float sc0[128];
    uint32_t sbase = smem_u32(smc);
    int tid = threadIdx.x, l = tid & 31, w = tid >> 5;
    int t0 = blockIdx.x*128, s0 = blockIdx.y*128;
    if (tid < 128) sc0[tid] = g_c0[s0 + tid];
    int wm0 = (w & 3)*32, wn0 = (w >> 2)*64;
    float acc[2][8][4];
#pragma unroll
    for (int i = 0; i < 2; i++)
#pragma unroll
        for (int n = 0; n < 8; n++)
#pragma unroll
            for (int q = 0; q < 4; q++) acc[i][n][q] = 0.f;

    int arow = ((l>>3)&1)*8 + (l&7);
    int akb  = (l>>4)*16;
    int brow = ((l>>4)&1)*8 + (l&7);
    int bkb  = ((l>>3)&1)*16;

    for (int kc = 0; kc < KPAD; kc += 64){
#pragma unroll
        for (int u = 0; u < 4; u++){
            int idx = tid + u*256; int row = idx >> 3, kq = idx & 7;
            uint32_t so = SW128(row*128 + kq*16);
            *(uint4*)(smc + so) =
                *(const uint4*)(g_Gt + (size_t)(t0+row)*KPAD + kc + kq*8);
            *(uint4*)(smc + 16384 + so) =
                *(const uint4*)(g_Wallb + (size_t)(s0+row)*KPAD + kc + kq*8);
        }
        __syncthreads();
#pragma unroll
        for (int ks = 0; ks < 4; ks++){
            uint32_t af[2][4], bf[8][2];
#pragma unroll
            for (int i = 0; i < 2; i++)
                ldsm4(af[i][0],af[i][1],af[i][2],af[i][3],
                      sbase + SW128((wm0+i*16+arow)*128 + ks*32 + akb));
#pragma unroll
            for (int j = 0; j < 4; j++)
                ldsm4(bf[2*j][0],bf[2*j][1],bf[2*j+1][0],bf[2*j+1][1],
                      sbase + 16384 + SW128((wn0+j*16+brow)*128 + ks*32 + bkb));
#pragma unroll
            for (int i = 0; i < 2; i++)
#pragma unroll
                for (int n = 0; n < 8; n++) mma16816(acc[i][n], af[i], bf[n]);
        }
        __syncthreads();
    }
    // stage bf16 tile [128][136] then coalesced store
    __nv_bfloat16* cs = (__nv_bfloat16*)smc;
#pragma unroll
    for (int i = 0; i < 2; i++){
        int r = wm0 + i*16 + (l>>2);
#pragma unroll
        for (int n = 0; n < 8; n++){
            int c = wn0 + n*8 + (l&3)*2;
            float b0 = sc0[c], b1 = sc0[c+1];
            *(__nv_bfloat162*)(cs + r*136 + c) =
                __floats2bfloat162_rn(fmaxf(acc[i][n][0]+b0,0.f), fmaxf(acc[i][n][1]+b1,0.f));
            *(__nv_bfloat162*)(cs + (r+8)*136 + c) =
                __floats2bfloat162_rn(fmaxf(acc[i][n][2]+b0,0.f), fmaxf(acc[i][n][3]+b1,0.f));
        }
    }
    __syncthreads();
#pragma unroll
    for (int u = 0; u < 8; u++){
        int idx = tid + u*256; int r = idx >> 4, c8 = idx & 15;
        *(uint4*)(g_ht + (size_t)(t0+r)*SD + s0 + c8*8) = *(const uint4*)(cs + r*136 + c8*8);
    }
}

// ---------------- HMMA GEMM3 + fused log_softmax ----------------
#define G3_SMEM 67840
__global__ void __launch_bounds__(256) k_hmma3(const float* __restrict__ bp2,
                                               float* __restrict__ out){
    extern __shared__ char smc[];
    __shared__ float sBias[256], sM[256], sS[256], sLZ[64];
    uint32_t sbase = smem_u32(smc);
    int tid = threadIdx.x, l = tid & 31, w = tid >> 5;
    int t0 = blockIdx.x*64;
    sBias[tid] = bp2[tid];
    int tm0 = (w & 3)*16, nh = w >> 2;
    float acc[16][4];
#pragma unroll
    for (int n = 0; n < 16; n++)
#pragma unroll
        for (int q = 0; q < 4; q++) acc[n][q] = 0.f;

    int arow = ((l>>3)&1)*8 + (l&7);
    int akb  = (l>>4)*16;
    int brow = ((l>>4)&1)*8 + (l&7);
    int bkb  = ((l>>3)&1)*16;

    for (int kc = 0; kc < SD; kc += 64){
#pragma unroll
        for (int u = 0; u < 2; u++){
            int idx = tid + u*256; int row = idx >> 3, kq = idx & 7;
            *(uint4*)(smc + SW128(row*128 + kq*16)) =
                *(const uint4*)(g_ht + (size_t)(t0+row)*SD + kc + kq*8);
        }
#pragma unroll
        for (int u = 0; u < 8; u++){
            int idx = tid + u*256; int row = idx >> 3, kq = idx & 7;
            *(uint4*)(smc + 8192 + SW128(row*128 + kq*16)) =
                *(const uint4*)(g_Wp2b + (size_t)row*SD + kc + kq*8);
        }
        __syncthreads();
#pragma unroll
        for (int ks = 0; ks < 4; ks++){
            uint32_t af[4], bf[16][2];
            ldsm4(af[0],af[1],af[2],af[3],
                  sbase + SW128((tm0+arow)*128 + ks*32 + akb));
#pragma unroll
            for (int j = 0; j < 8; j++)
                ldsm4(bf[2*j][0],bf[2*j][1],bf[2*j+1][0],bf[2*j+1][1],
                      sbase + 8192 + SW128((nh*128+j*16+brow)*128 + ks*32 + bkb));
#pragma unroll
            for (int n = 0; n < 16; n++) mma16816(acc[n], af, bf[n]);
        }
        __syncthreads();
    }
    // stage f32 C [64][265] with bias
    float* cs = (float*)smc;
    {
        int r = tm0 + (l>>2);
#pragma unroll
        for (int n = 0; n < 16; n++){
            int q = nh*128 + n*8 + (l&3)*2;
            cs[r*265 + q]       = acc[n][0] + sBias[q];
            cs[r*265 + q + 1]   = acc[n][1] + sBias[q+1];
            cs[(r+8)*265 + q]   = acc[n][2] + sBias[q];
            cs[(r+8)*265 + q+1] = acc[n][3] + sBias[q+1];
        }
    }
    __syncthreads();
    int tt = tid & 63, qg = tid >> 6;
    float m = -1e30f;
#pragma unroll 8
    for (int j = 0; j < 64; j++) m = fmaxf(m, cs[tt*265 + qg*64 + j]);
    float s = 0.f;
#pragma unroll 8
    for (int j = 0; j < 64; j++) s += __expf(cs[tt*265 + qg*64 + j] - m);
    sM[qg*64 + tt] = m; sS[qg*64 + tt] = s;
    __syncthreads();
    if (qg == 0){
        float mm = sM[tt];
#pragma unroll
        for (int g = 1; g < 4; g++) mm = fmaxf(mm, sM[g*64 + tt]);
        float ss = 0.f;
#pragma unroll
        for (int g = 0; g < 4; g++) ss += sS[g*64 + tt]*__expf(sM[g*64 + tt] - mm);
        sLZ[tt] = mm + logf(ss);
    }
    __syncthreads();
    float lz = sLZ[tt];
#pragma unroll 8
    for (int j = 0; j < 64; j++){
        int q = qg*64 + j;
        out[(size_t)q*T_LEN + t0 + tt] = cs[tt*265 + q] - lz;
    }
}

// ---------------- launch ----------------
extern "C" void kernel_launch(void* const* d_in, const int* in_sizes, int n_in,
                              void* d_out, int out_size){
    const float* x     = (const float*)d_in[0];
    const float* Wc    = (const float*)d_in[1];
    const float* bc    = (const float*)d_in[2];
    const float* Wt    = (const float*)d_in[3];
    const float* bt    = (const float*)d_in[4];
    const float* Ws    = (const float*)d_in[5];
    const float* bs    = (const float*)d_in[6];
    const float* Wskip = (const float*)d_in[7];
    const float* bskip = (const float*)d_in[8];
    const float* Wd    = (const float*)d_in[9];
    const float* bd    = (const float*)d_in[10];
    const float* Wp1   = (const float*)d_in[11];
    const float* bp1   = (const float*)d_in[12];
    const float* Wp2   = (const float*)d_in[13];
    const float* bp2   = (const float*)d_in[14];
    float* out = (float*)d_out;

    static const int DIL[NL] = {1,2,4,8,16,32,64,128,256,
                                1,2,4,8,16,32,64,128,256,
                                1,2,4,8,16,32,64,128,256};

    cudaFuncSetAttribute(k_layer, cudaFuncAttributeMaxDynamicSharedMemorySize, LSMEM_F*4);
    cudaFuncSetAttribute(k_hmma2, cudaFuncAttributeMaxDynamicSharedMemorySize, G2_SMEM);
    cudaFuncSetAttribute(k_hmma3, cudaFuncAttributeMaxDynamicSharedMemorySize, G3_SMEM);

    // layers first so ncu (-s 5) lands on a k_layer
    k_conv0<<<T_LEN/256, 256>>>(x, Wc, bc);
    for (int i = 0; i < NL; i++)
        k_layer<<<T_LEN/128, 256, LSMEM_F*4>>>(Wt, bt, Ws, bs, Wd, bd, i, DIL[i]);
    k_bsum<<<2, 256>>>(bskip);
    k_c0<<<SD, 128>>>(Wp1, bp1);
    k_fold<<<32, 864>>>(Wp1, Wskip);
    k_cvtWall<<<SD, 256>>>();
    k_cvtWp2<<<QD, 256>>>(Wp2);
    k_padG<<<T_LEN/256, 256>>>();
    k_hmma2<<<dim3(T_LEN/128, SD/128), 256, G2_SMEM>>>();
    k_hmma3<<<T_LEN/64, 256, G3_SMEM>>>(bp2, out);
}

// round 16
// speedup vs baseline: 7.6441x; 4.9832x over previous
#include <cuda_runtime.h>
#include <cuda_bf16.h>
#include <math.h>
#include <stdint.h>

#define T_LEN 131072
#define NL 27
#define SD 512
#define QD 256
#define KC (NL*32)
#define KPAD 896
#define TT 128

typedef unsigned long long u64;

__device__ float g_x0[32*(size_t)T_LEN];
__device__ float g_x1[32*(size_t)T_LEN];
__device__ __nv_bfloat16 g_Gt[(size_t)T_LEN*KPAD];
__device__ __nv_bfloat16 g_ht[(size_t)T_LEN*SD];
__device__ float g_Wall[SD*KC];
__device__ __nv_bfloat16 g_Wallb[SD*KPAD];
__device__ __nv_bfloat16 g_Wp2b[QD*SD];
__device__ float g_c0[SD];
__device__ float g_bsum[SD];

__device__ __forceinline__ uint32_t smem_u32(const void* p){
    uint32_t a; asm("{ .reg .u64 t; cvta.to.shared.u64 t, %1; cvt.u32.u64 %0, t; }":"=r"(a):"l"(p)); return a;
}
#define SW128(o) ((uint32_t)(o) ^ ((((uint32_t)(o))>>3)&0x70u))

__device__ __forceinline__ void ldsm4(uint32_t &r0,uint32_t &r1,uint32_t &r2,uint32_t &r3,uint32_t a){
    asm volatile("ldmatrix.sync.aligned.m8n8.x4.shared.b16 {%0,%1,%2,%3}, [%4];"
        : "=r"(r0),"=r"(r1),"=r"(r2),"=r"(r3) : "r"(a));
}
__device__ __forceinline__ void ldsm4t(uint32_t &r0,uint32_t &r1,uint32_t &r2,uint32_t &r3,uint32_t a){
    asm volatile("ldmatrix.sync.aligned.m8n8.x4.trans.shared.b16 {%0,%1,%2,%3}, [%4];"
        : "=r"(r0),"=r"(r1),"=r"(r2),"=r"(r3) : "r"(a));
}
__device__ __forceinline__ void mma16816(float* c, const uint32_t* a, const uint32_t* b){
    asm volatile("mma.sync.aligned.m16n8k16.row.col.f32.bf16.bf16.f32 "
        "{%0,%1,%2,%3}, {%4,%5,%6,%7}, {%8,%9}, {%0,%1,%2,%3};"
        : "+f"(c[0]),"+f"(c[1]),"+f"(c[2]),"+f"(c[3])
        : "r"(a[0]),"r"(a[1]),"r"(a[2]),"r"(a[3]),"r"(b[0]),"r"(b[1]));
}

// ---------------- small kernels ----------------
__global__ void k_padG(){
    size_t t = blockIdx.x*256 + threadIdx.x;
    uint4 z = make_uint4(0,0,0,0);
    uint4* d = (uint4*)(g_Gt + t*KPAD + KC);
    d[0] = z; d[1] = z; d[2] = z; d[3] = z;
}
__global__ void k_conv0(const float* __restrict__ x, const float* __restrict__ Wc,
                        const float* __restrict__ bc){
    __shared__ float4 w[32];
    int tid = threadIdx.x;
    if (tid < 32) w[tid] = make_float4(Wc[tid*3], Wc[tid*3+1], Wc[tid*3+2], bc[tid]);
    __syncthreads();
    int t = blockIdx.x*256 + tid;
    float xm = (t > 0)       ? x[t-1] : 0.f;
    float x0 = x[t];
    float xp = (t < T_LEN-1) ? x[t+1] : 0.f;
#pragma unroll
    for (int o = 0; o < 32; o++){
        float4 q = w[o];
        g_x0[(size_t)o*T_LEN + t] = q.w + q.x*xm + q.y*x0 + q.z*xp;
    }
}
__global__ void k_bsum(const float* __restrict__ bskip){
    int m = blockIdx.x*256 + threadIdx.x;
    if (m < SD){
        float s = 0.f;
        for (int i = 0; i < NL; i++) s += bskip[i*SD + m];
        g_bsum[m] = s;
    }
}
__global__ void k_c0(const float* __restrict__ Wp1, const float* __restrict__ bp1){
    __shared__ float red[128];
    int s = blockIdx.x, tid = threadIdx.x;
    float acc = 0.f;
    for (int m = tid; m < SD; m += 128) acc += Wp1[s*SD + m]*g_bsum[m];
    red[tid] = acc; __syncthreads();
    for (int st = 64; st > 0; st >>= 1){
        if (tid < st) red[tid] += red[tid+st];
        __syncthreads();
    }
    if (tid == 0) g_c0[s] = red[0] + bp1[s];
}
__global__ void k_fold(const float* __restrict__ Wp1, const float* __restrict__ Wsk){
    __shared__ float wr[16*512];
    int s0 = blockIdx.x*16, tid = threadIdx.x;
    for (int i = tid; i < 16*512; i += 864)
        wr[i] = Wp1[(size_t)(s0 + (i>>9))*SD + (i & 511)];
    __syncthreads();
    int i = tid >> 5, c = tid & 31;
    float acc[16];
#pragma unroll
    for (int u = 0; u < 16; u++) acc[u] = 0.f;
    const float* wp = Wsk + (size_t)i*SD*32 + c;
    for (int m = 0; m < SD; m++){
        float v = wp[m*32];
#pragma unroll
        for (int u = 0; u < 16; u++) acc[u] += wr[u*512 + m]*v;
    }
#pragma unroll
    for (int u = 0; u < 16; u++) g_Wall[(s0+u)*KC + tid] = acc[u];
}
__global__ void k_cvtWall(){
    int row = blockIdx.x;
    for (int k = threadIdx.x; k < KPAD; k += 256)
        g_Wallb[row*KPAD + k] = __float2bfloat16(k < KC ? g_Wall[row*KC + k] : 0.f);
}
__global__ void k_cvtWp2(const float* __restrict__ Wp2){
    int row = blockIdx.x;
    for (int k = threadIdx.x; k < SD; k += 256)
        g_Wp2b[row*SD + k] = __float2bfloat16(Wp2[row*SD + k]);
}

// ---------------- WaveNet layer via HMMA ----------------
// smem: sXs[96][136]bf16 @0 (26112) | sWa[32][104]bf16 @26112 (6656) |
//       sWb @32768 (6656) | sWd[32][40]bf16 @39424 (2560) | biases @41984 (384)
#define LSMEM 42368
__global__ void __launch_bounds__(256) k_layer(
    const float* __restrict__ Wt, const float* __restrict__ bt,
    const float* __restrict__ Ws, const float* __restrict__ bs,
    const float* __restrict__ Wd, const float* __restrict__ bd,
    int layer, int dil)
{
    extern __shared__ char smc[];
    __nv_bfloat16* sXs = (__nv_bfloat16*)smc;
    __nv_bfloat16* sWa = (__nv_bfloat16*)(smc + 26112);
    __nv_bfloat16* sWb = (__nv_bfloat16*)(smc + 32768);
    __nv_bfloat16* sWd = (__nv_bfloat16*)(smc + 39424);
    float* sbt = (float*)(smc + 41984);
    float* sbs = sbt + 32; float* sbd = sbt + 64;

    const float* xin  = (layer & 1) ? g_x1 : g_x0;
    float*       xout = (layer & 1) ? g_x0 : g_x1;
    int tid = threadIdx.x;
    int tb  = blockIdx.x*TT;

    // weights -> bf16 smem
    const float* Wtl = Wt + layer*3072;
    const float* Wsl = Ws + layer*3072;
    for (int i = tid; i < 3072; i += 256){
        int o = i/96, ck = i - o*96;
        sWa[o*104 + ck] = __float2bfloat16(Wtl[i]);
        sWb[o*104 + ck] = __float2bfloat16(Wsl[i]);
    }
    for (int i = tid; i < 1024; i += 256)
        sWd[(i>>5)*40 + (i&31)] = __float2bfloat16(Wd[layer*1024 + i]);
    if (tid < 32){ sbt[tid]=bt[layer*32+tid]; sbs[tid]=bs[layer*32+tid]; sbd[tid]=bd[layer*32+tid]; }

    // Xs[(c*3+k)][t] = bf16(x[c][tb+t+(k-1)d]); 96 rows x 128 t, 2 t per thread-iter
#pragma unroll 4
    for (int u = 0; u < 24; u++){
        int idx = tid + u*256;
        int row = idx >> 6, tq = idx & 63;
        int c = row/3, k = row - c*3;
        long t = (long)tb + tq*2 + (k-1)*dil;
        const float* xc = xin + (size_t)c*T_LEN;
        float f0 = (t   >= 0 && t   < T_LEN) ? xc[t]   : 0.f;
        float f1 = (t+1 >= 0 && t+1 < T_LEN) ? xc[t+1] : 0.f;
        *(__nv_bfloat162*)(sXs + row*136 + tq*2) = __floats2bfloat162_rn(f0, f1);
    }
    __syncthreads();

    int w = tid >> 5, l = tid & 31;
    int m0 = w*16;
    uint32_t sb32 = smem_u32(smc);

    // A (ldmatrix.trans from [k][t]): row = k0 + 8*((l>>4)&1) + (l&7), col = m0 + 8*((l>>3)&1)
    uint32_t aAddr = sb32 + (uint32_t)(((8*((l>>4)&1) + (l&7))*136 + m0 + 8*((l>>3)&1))*2);
    // B (proven non-trans pattern): row = 8*((l>>4)&1) + (l&7), kbytes = 16*((l>>3)&1)
    uint32_t brow = ((l>>4)&1)*8 + (l&7);
    uint32_t bkb  = ((l>>3)&1)*16;
    uint32_t baA = sb32 + 26112u + brow*208 + bkb;
    uint32_t baB = sb32 + 32768u + brow*208 + bkb;
    uint32_t baD = sb32 + 39424u + brow*80  + bkb;

    float aa[4][4], ab[4][4];
#pragma unroll
    for (int j = 0; j < 4; j++)
#pragma unroll
        for (int q = 0; q < 4; q++){ aa[j][q] = 0.f; ab[j][q] = 0.f; }

#pragma unroll
    for (int kk = 0; kk < 6; kk++){
        uint32_t af[4];
        ldsm4t(af[0],af[1],af[2],af[3], aAddr + kk*16*272);
        uint32_t bfa[4][2], bfb[4][2];
#pragma unroll
        for (int j = 0; j < 2; j++){
            ldsm4(bfa[2*j][0],bfa[2*j][1],bfa[2*j+1][0],bfa[2*j+1][1], baA + j*16*208 + kk*32);
            ldsm4(bfb[2*j][0],bfb[2*j][1],bfb[2*j+1][0],bfb[2*j+1][1], baB + j*16*208 + kk*32);
        }
#pragma unroll
        for (int j = 0; j < 4; j++){
            mma16816(aa[j], af, bfa[j]);
            mma16816(ab[j], af, bfb[j]);
        }
    }

    // activation: g = tanh(a+bt)*sigmoid(b+bs); pack to dense A-frags + Gt store
    int ti2 = 2*(l&3);
    long trow = (long)tb + m0 + (l>>2);
    uint32_t ga[2][4];
#pragma unroll
    for (int j = 0; j < 4; j++){
        int o = 8*j + ti2;
        float bt0 = sbt[o], bt1 = sbt[o+1];
        float bs0 = sbs[o], bs1 = sbs[o+1];
        float gv[4];
#pragma unroll
        for (int q = 0; q < 4; q++){
            float av = aa[j][q] + ((q&1) ? bt1 : bt0);
            float bv = ab[j][q] + ((q&1) ? bs1 : bs0);
            float e  = __expf(2.f*fminf(fmaxf(av, -15.f), 15.f));
            float th = __fdividef(e - 1.f, e + 1.f);
            float sg = __fdividef(1.f, 1.f + __expf(-bv));
            gv[q] = th*sg;
        }
        __nv_bfloat162 p0 = __floats2bfloat162_rn(gv[0], gv[1]);
        __nv_bfloat162 p1 = __floats2bfloat162_rn(gv[2], gv[3]);
        *(uint32_t*)(g_Gt + (size_t)trow*KPAD     + layer*32 + o) = *(uint32_t*)&p0;
        *(uint32_t*)(g_Gt + (size_t)(trow+8)*KPAD + layer*32 + o) = *(uint32_t*)&p1;
        ga[j>>1][(j&1)*2 + 0] = *(uint32_t*)&p0;
        ga[j>>1][(j&1)*2 + 1] = *(uint32_t*)&p1;
    }

    // dense: xout = g @ Wd^T + bd + xin
    float da[4][4];
#pragma unroll
    for (int j = 0; j < 4; j++)
#pragma unroll
        for (int q = 0; q < 4; q++) da[j][q] = 0.f;
#pragma unroll
    for (int kt = 0; kt < 2; kt++){
        uint32_t bfd[4][2];
#pragma unroll
        for (int j = 0; j < 2; j++)
            ldsm4(bfd[2*j][0],bfd[2*j][1],bfd[2*j+1][0],bfd[2*j+1][1], baD + j*16*80 + kt*32);
#pragma unroll
        for (int j = 0; j < 4; j++) mma16816(da[j], ga[kt], bfd[j]);
    }
#pragma unroll
    for (int j = 0; j < 4; j++){
        int o = 8*j + ti2;
        float b0 = sbd[o], b1 = sbd[o+1];
        size_t i00 = (size_t)o*T_LEN + trow;
        size_t i10 = (size_t)(o+1)*T_LEN + trow;
        xout[i00]     = da[j][0] + b0 + xin[i00];
        xout[i10]     = da[j][1] + b1 + xin[i10];
        xout[i00 + 8] = da[j][2] + b0 + xin[i00 + 8];
        xout[i10 + 8] = da[j][3] + b1 + xin[i10 + 8];
    }
}

// ---------------- HMMA GEMM2: ht = relu(Gt @ Wallb^T + c0), bf16 out ----------------
#define G2_SMEM 34816
__global__ void __launch_bounds__(256) k_hmma2(){
    extern __shared__ char smc[];
    __shared__ float sc0[128];
    uint32_t sbase = smem_u32(smc);
    int tid = threadIdx.x, l = tid & 31, w = tid >> 5;
    int t0 = blockIdx.x*128, s0 = blockIdx.y*128;
    if (tid < 128) sc0[tid] = g_c0[s0 + tid];
    int wm0 = (w & 3)*32, wn0 = (w >> 2)*64;
    float acc[2][8][4];
#pragma unroll
    for (int i = 0; i < 2; i++)
#pragma unroll
        for (int n = 0; n < 8; n++)
#pragma unroll
            for (int q = 0; q < 4; q++) acc[i][n][q] = 0.f;

    int arow = ((l>>3)&1)*8 + (l&7);
    int akb  = (l>>4)*16;
    int brow = ((l>>4)&1)*8 + (l&7);
    int bkb  = ((l>>3)&1)*16;

    for (int kc = 0; kc < KPAD; kc += 64){
#pragma unroll
        for (int u = 0; u < 4; u++){
            int idx = tid + u*256; int row = idx >> 3, kq = idx & 7;
            uint32_t so = SW128(row*128 + kq*16);
            *(uint4*)(smc + so) =
                *(const uint4*)(g_Gt + (size_t)(t0+row)*KPAD + kc + kq*8);
            *(uint4*)(smc + 16384 + so) =
                *(const uint4*)(g_Wallb + (size_t)(s0+row)*KPAD + kc + kq*8);
        }
        __syncthreads();
#pragma unroll
        for (int ks = 0; ks < 4; ks++){
            uint32_t af[2][4], bf[8][2];
#pragma unroll
            for (int i = 0; i < 2; i++)
                ldsm4(af[i][0],af[i][1],af[i][2],af[i][3],
                      sbase + SW128((wm0+i*16+arow)*128 + ks*32 + akb));
#pragma unroll
            for (int j = 0; j < 4; j++)
                ldsm4(bf[2*j][0],bf[2*j][1],bf[2*j+1][0],bf[2*j+1][1],
                      sbase + 16384 + SW128((wn0+j*16+brow)*128 + ks*32 + bkb));
#pragma unroll
            for (int i = 0; i < 2; i++)
#pragma unroll
                for (int n = 0; n < 8; n++) mma16816(acc[i][n], af[i], bf[n]);
        }
        __syncthreads();
    }
    __nv_bfloat16* cs = (__nv_bfloat16*)smc;
#pragma unroll
    for (int i = 0; i < 2; i++){
        int r = wm0 + i*16 + (l>>2);
#pragma unroll
        for (int n = 0; n < 8; n++){
            int c = wn0 + n*8 + (l&3)*2;
            float b0 = sc0[c], b1 = sc0[c+1];
            *(__nv_bfloat162*)(cs + r*136 + c) =
                __floats2bfloat162_rn(fmaxf(acc[i][n][0]+b0,0.f), fmaxf(acc[i][n][1]+b1,0.f));
            *(__nv_bfloat162*)(cs + (r+8)*136 + c) =
                __floats2bfloat162_rn(fmaxf(acc[i][n][2]+b0,0.f), fmaxf(acc[i][n][3]+b1,0.f));
        }
    }
    __syncthreads();
#pragma unroll
    for (int u = 0; u < 8; u++){
        int idx = tid + u*256; int r = idx >> 4, c8 = idx & 15;
        *(uint4*)(g_ht + (size_t)(t0+r)*SD + s0 + c8*8) = *(const uint4*)(cs + r*136 + c8*8);
    }
}

// ---------------- HMMA GEMM3 + fused log_softmax ----------------
#define G3_SMEM 67840
__global__ void __launch_bounds__(256) k_hmma3(const float* __restrict__ bp2,
                                               float* __restrict__ out){
    extern __shared__ char smc[];
    __shared__ float sBias[256], sM[256], sS[256], sLZ[64];
    uint32_t sbase = smem_u32(smc);
    int tid = threadIdx.x, l = tid & 31, w = tid >> 5;
    int t0 = blockIdx.x*64;
    sBias[tid] = bp2[tid];
    int tm0 = (w & 3)*16, nh = w >> 2;
    float acc[16][4];
#pragma unroll
    for (int n = 0; n < 16; n++)
#pragma unroll
        for (int q = 0; q < 4; q++) acc[n][q] = 0.f;

    int arow = ((l>>3)&1)*8 + (l&7);
    int akb  = (l>>4)*16;
    int brow = ((l>>4)&1)*8 + (l&7);
    int bkb  = ((l>>3)&1)*16;

    for (int kc = 0; kc < SD; kc += 64){
#pragma unroll
        for (int u = 0; u < 2; u++){
            int idx = tid + u*256; int row = idx >> 3, kq = idx & 7;
            *(uint4*)(smc + SW128(row*128 + kq*16)) =
                *(const uint4*)(g_ht + (size_t)(t0+row)*SD + kc + kq*8);
        }
#pragma unroll
        for (int u = 0; u < 8; u++){
            int idx = tid + u*256; int row = idx >> 3, kq = idx & 7;
            *(uint4*)(smc + 8192 + SW128(row*128 + kq*16)) =
                *(const uint4*)(g_Wp2b + (size_t)row*SD + kc + kq*8);
        }
        __syncthreads();
#pragma unroll
        for (int ks = 0; ks < 4; ks++){
            uint32_t af[4], bf[16][2];
            ldsm4(af[0],af[1],af[2],af[3],
                  sbase + SW128((tm0+arow)*128 + ks*32 + akb));
#pragma unroll
            for (int j = 0; j < 8; j++)
                ldsm4(bf[2*j][0],bf[2*j][1],bf[2*j+1][0],bf[2*j+1][1],
                      sbase + 8192 + SW128((nh*128+j*16+brow)*128 + ks*32 + bkb));
#pragma unroll
            for (int n = 0; n < 16; n++) mma16816(acc[n], af, bf[n]);
        }
        __syncthreads();
    }
    float* cs = (float*)smc;
    {
        int r = tm0 + (l>>2);
#pragma unroll
        for (int n = 0; n < 16; n++){
            int q = nh*128 + n*8 + (l&3)*2;
            cs[r*265 + q]       = acc[n][0] + sBias[q];
            cs[r*265 + q + 1]   = acc[n][1] + sBias[q+1];
            cs[(r+8)*265 + q]   = acc[n][2] + sBias[q];
            cs[(r+8)*265 + q+1] = acc[n][3] + sBias[q+1];
        }
    }
    __syncthreads();
    int tt = tid & 63, qg = tid >> 6;
    float m = -1e30f;
#pragma unroll 8
    for (int j = 0; j < 64; j++) m = fmaxf(m, cs[tt*265 + qg*64 + j]);
    float s = 0.f;
#pragma unroll 8
    for (int j = 0; j < 64; j++) s += __expf(cs[tt*265 + qg*64 + j] - m);
    sM[qg*64 + tt] = m; sS[qg*64 + tt] = s;
    __syncthreads();
    if (qg == 0){
        float mm = sM[tt];
#pragma unroll
        for (int g = 1; g < 4; g++) mm = fmaxf(mm, sM[g*64 + tt]);
        float ss = 0.f;
#pragma unroll
        for (int g = 0; g < 4; g++) ss += sS[g*64 + tt]*__expf(sM[g*64 + tt] - mm);
        sLZ[tt] = mm + logf(ss);
    }
    __syncthreads();
    float lz = sLZ[tt];
#pragma unroll 8
    for (int j = 0; j < 64; j++){
        int q = qg*64 + j;
        out[(size_t)q*T_LEN + t0 + tt] = cs[tt*265 + q] - lz;
    }
}

// ---------------- launch ----------------
extern "C" void kernel_launch(void* const* d_in, const int* in_sizes, int n_in,
                              void* d_out, int out_size){
    const float* x     = (const float*)d_in[0];
    const float* Wc    = (const float*)d_in[1];
    const float* bc    = (const float*)d_in[2];
    const float* Wt    = (const float*)d_in[3];
    const float* bt    = (const float*)d_in[4];
    const float* Ws    = (const float*)d_in[5];
    const float* bs    = (const float*)d_in[6];
    const float* Wskip = (const float*)d_in[7];
    const float* bskip = (const float*)d_in[8];
    const float* Wd    = (const float*)d_in[9];
    const float* bd    = (const float*)d_in[10];
    const float* Wp1   = (const float*)d_in[11];
    const float* bp1   = (const float*)d_in[12];
    const float* Wp2   = (const float*)d_in[13];
    const float* bp2   = (const float*)d_in[14];
    float* out = (float*)d_out;

    static const int DIL[NL] = {1,2,4,8,16,32,64,128,256,
                                1,2,4,8,16,32,64,128,256,
                                1,2,4,8,16,32,64,128,256};

    cudaFuncSetAttribute(k_layer, cudaFuncAttributeMaxDynamicSharedMemorySize, LSMEM);
    cudaFuncSetAttribute(k_hmma2, cudaFuncAttributeMaxDynamicSharedMemorySize, G2_SMEM);
    cudaFuncSetAttribute(k_hmma3, cudaFuncAttributeMaxDynamicSharedMemorySize, G3_SMEM);

    k_conv0<<<T_LEN/256, 256>>>(x, Wc, bc);
    for (int i = 0; i < NL; i++)
        k_layer<<<T_LEN/TT, 256, LSMEM>>>(Wt, bt, Ws, bs, Wd, bd, i, DIL[i]);
    k_bsum<<<2, 256>>>(bskip);
    k_c0<<<SD, 128>>>(Wp1, bp1);
    k_fold<<<32, 864>>>(Wp1, Wskip);
    k_cvtWall<<<SD, 256>>>();
    k_cvtWp2<<<QD, 256>>>(Wp2);
    k_padG<<<T_LEN/256, 256>>>();
    k_hmma2<<<dim3(T_LEN/128, SD/128), 256, G2_SMEM>>>();
    k_hmma3<<<T_LEN/64, 256, G3_SMEM>>>(bp2, out);
}

// round 17
// speedup vs baseline: 11.6052x; 1.5182x over previous
#include <cuda_runtime.h>
#include <cuda_bf16.h>
#include <math.h>
#include <stdint.h>

#define T_LEN 131072
#define NL 27
#define SD 512
#define QD 256
#define KC (NL*32)
#define KPAD 896
#define TT 128

typedef unsigned long long u64;

__device__ float g_x0[32*(size_t)T_LEN];
__device__ float g_x1[32*(size_t)T_LEN];
__device__ __nv_bfloat16 g_Gt[(size_t)T_LEN*KPAD];
__device__ __nv_bfloat16 g_ht[(size_t)T_LEN*SD];
__device__ float g_Wall[SD*KC];
__device__ __nv_bfloat16 g_Wallb[SD*KPAD];
__device__ __nv_bfloat16 g_Wp2b[QD*SD];
__device__ __nv_bfloat16 g_Wab[NL*6656];   // per layer: [a|b][32][104]
__device__ __nv_bfloat16 g_Wdb[NL*1280];   // per layer: [32][40]
__device__ float g_c0[SD];
__device__ float g_bsum[SD];

__device__ __forceinline__ uint32_t smem_u32(const void* p){
    uint32_t a; asm("{ .reg .u64 t; cvta.to.shared.u64 t, %1; cvt.u32.u64 %0, t; }":"=r"(a):"l"(p)); return a;
}
#define SW128(o) ((uint32_t)(o) ^ ((((uint32_t)(o))>>3)&0x70u))

__device__ __forceinline__ void ldsm4(uint32_t &r0,uint32_t &r1,uint32_t &r2,uint32_t &r3,uint32_t a){
    asm volatile("ldmatrix.sync.aligned.m8n8.x4.shared.b16 {%0,%1,%2,%3}, [%4];"
        : "=r"(r0),"=r"(r1),"=r"(r2),"=r"(r3) : "r"(a));
}
__device__ __forceinline__ void ldsm4t(uint32_t &r0,uint32_t &r1,uint32_t &r2,uint32_t &r3,uint32_t a){
    asm volatile("ldmatrix.sync.aligned.m8n8.x4.trans.shared.b16 {%0,%1,%2,%3}, [%4];"
        : "=r"(r0),"=r"(r1),"=r"(r2),"=r"(r3) : "r"(a));
}
__device__ __forceinline__ void mma16816(float* c, const uint32_t* a, const uint32_t* b){
    asm volatile("mma.sync.aligned.m16n8k16.row.col.f32.bf16.bf16.f32 "
        "{%0,%1,%2,%3}, {%4,%5,%6,%7}, {%8,%9}, {%0,%1,%2,%3};"
        : "+f"(c[0]),"+f"(c[1]),"+f"(c[2]),"+f"(c[3])
        : "r"(a[0]),"r"(a[1]),"r"(a[2]),"r"(a[3]),"r"(b[0]),"r"(b[1]));
}
__device__ __forceinline__ float tanh_ap(float x){ float r; asm("tanh.approx.f32 %0,%1;":"=f"(r):"f"(x)); return r; }

#define CPA16(d,s) asm volatile("cp.async.cg.shared.global [%0], [%1], 16;" :: "r"(d), "l"(s))
#define CPCG()     asm volatile("cp.async.commit_group;" ::: "memory")
#define CPWG(n)    asm volatile("cp.async.wait_group %0;" :: "n"(n) : "memory")

// ---------------- small kernels ----------------
__global__ void k_padG(){
    size_t t = blockIdx.x*256 + threadIdx.x;
    uint4 z = make_uint4(0,0,0,0);
    uint4* d = (uint4*)(g_Gt + t*KPAD + KC);
    d[0] = z; d[1] = z; d[2] = z; d[3] = z;
}
__global__ void k_conv0(const float* __restrict__ x, const float* __restrict__ Wc,
                        const float* __restrict__ bc){
    __shared__ float4 w[32];
    int tid = threadIdx.x;
    if (tid < 32) w[tid] = make_float4(Wc[tid*3], Wc[tid*3+1], Wc[tid*3+2], bc[tid]);
    __syncthreads();
    int t = blockIdx.x*256 + tid;
    float xm = (t > 0)       ? x[t-1] : 0.f;
    float x0 = x[t];
    float xp = (t < T_LEN-1) ? x[t+1] : 0.f;
#pragma unroll
    for (int o = 0; o < 32; o++){
        float4 q = w[o];
        g_x0[(size_t)o*T_LEN + t] = q.w + q.x*xm + q.y*x0 + q.z*xp;
    }
}
__global__ void k_cvtW(const float* __restrict__ Wt, const float* __restrict__ Ws,
                       const float* __restrict__ Wd){
    int l = blockIdx.x, tid = threadIdx.x;
    __nv_bfloat16* wa = g_Wab + l*6656;
    for (int i = tid; i < 3072; i += 256){
        int o = i/96, ck = i - o*96;
        wa[o*104 + ck]        = __float2bfloat16(Wt[l*3072 + i]);
        wa[3328 + o*104 + ck] = __float2bfloat16(Ws[l*3072 + i]);
    }
    __nv_bfloat16* wd = g_Wdb + l*1280;
    for (int i = tid; i < 1024; i += 256)
        wd[(i>>5)*40 + (i&31)] = __float2bfloat16(Wd[l*1024 + i]);
}
__global__ void k_bsum(const float* __restrict__ bskip){
    int m = blockIdx.x*256 + threadIdx.x;
    if (m < SD){
        float s = 0.f;
        for (int i = 0; i < NL; i++) s += bskip[i*SD + m];
        g_bsum[m] = s;
    }
}
__global__ void k_c0(const float* __restrict__ Wp1, const float* __restrict__ bp1){
    __shared__ float red[128];
    int s = blockIdx.x, tid = threadIdx.x;
    float acc = 0.f;
    for (int m = tid; m < SD; m += 128) acc += Wp1[s*SD + m]*g_bsum[m];
    red[tid] = acc; __syncthreads();
    for (int st = 64; st > 0; st >>= 1){
        if (tid < st) red[tid] += red[tid+st];
        __syncthreads();
    }
    if (tid == 0) g_c0[s] = red[0] + bp1[s];
}
__global__ void k_fold(const float* __restrict__ Wp1, const float* __restrict__ Wsk){
    __shared__ float wr[16*512];
    int s0 = blockIdx.x*16, tid = threadIdx.x;
    for (int i = tid; i < 16*512; i += 864)
        wr[i] = Wp1[(size_t)(s0 + (i>>9))*SD + (i & 511)];
    __syncthreads();
    int i = tid >> 5, c = tid & 31;
    float acc[16];
#pragma unroll
    for (int u = 0; u < 16; u++) acc[u] = 0.f;
    const float* wp = Wsk + (size_t)i*SD*32 + c;
    for (int m = 0; m < SD; m++){
        float v = wp[m*32];
#pragma unroll
        for (int u = 0; u < 16; u++) acc[u] += wr[u*512 + m]*v;
    }
#pragma unroll
    for (int u = 0; u < 16; u++) g_Wall[(s0+u)*KC + tid] = acc[u];
}
__global__ void k_cvtWall(){
    int row = blockIdx.x;
    for (int k = threadIdx.x; k < KPAD; k += 256)
        g_Wallb[row*KPAD + k] = __float2bfloat16(k < KC ? g_Wall[row*KC + k] : 0.f);
}
__global__ void k_cvtWp2(const float* __restrict__ Wp2){
    int row = blockIdx.x;
    for (int k = threadIdx.x; k < SD; k += 256)
        g_Wp2b[row*SD + k] = __float2bfloat16(Wp2[row*SD + k]);
}

// ---------------- WaveNet layer via HMMA ----------------
// smem: sXs[96][136]bf16 @0 (26112) | sWa @26112 (6656) | sWb @32768 (6656) |
//       sWd @39424 (2560) | biases @41984 (384)
#define LSMEM 42368
__global__ void __launch_bounds__(256) k_layer(
    const float* __restrict__ bt, const float* __restrict__ bs,
    const float* __restrict__ bd, int layer, int dil)
{
    extern __shared__ char smc[];
    __nv_bfloat16* sXs = (__nv_bfloat16*)smc;
    float* sbt = (float*)(smc + 41984);
    float* sbs = sbt + 32; float* sbd = sbt + 64;

    const float* xin  = (layer & 1) ? g_x1 : g_x0;
    float*       xout = (layer & 1) ? g_x0 : g_x1;
    int tid = threadIdx.x;
    int tb  = blockIdx.x*TT;

    // bf16 weight copy (pre-converted, contiguous a|b block)
    {
        const uint4* srcA = (const uint4*)(g_Wab + layer*6656);
        uint4* dA = (uint4*)(smc + 26112);
#pragma unroll
        for (int u = 0; u < 4; u++){
            int i = tid + u*256;
            if (i < 832) dA[i] = srcA[i];
        }
        const uint4* srcD = (const uint4*)(g_Wdb + layer*1280);
        if (tid < 160) ((uint4*)(smc + 39424))[tid] = srcD[tid];
        if (tid < 32){ sbt[tid]=bt[layer*32+tid]; sbs[tid]=bs[layer*32+tid]; sbd[tid]=bd[layer*32+tid]; }
    }

    // Xs fill: division-free, interior fast path
    {
        int rg = tid >> 6;            // channel group: rg*8 .. rg*8+7
        int tq = (tid & 63)*2;
        if (tb >= dil && tb + TT + dil <= T_LEN){
#pragma unroll
            for (int c8 = 0; c8 < 8; c8++){
                int c = rg*8 + c8;
                const float* xc = xin + (size_t)c*T_LEN + tb + tq;
                float m0 = xc[-dil], m1 = xc[1-dil];
                float z0 = xc[0],    z1 = xc[1];
                float p0 = xc[dil],  p1 = xc[dil+1];
                __nv_bfloat16* rowp = sXs + (c*3)*136 + tq;
                *(__nv_bfloat162*)(rowp)       = __floats2bfloat162_rn(m0, m1);
                *(__nv_bfloat162*)(rowp + 136) = __floats2bfloat162_rn(z0, z1);
                *(__nv_bfloat162*)(rowp + 272) = __floats2bfloat162_rn(p0, p1);
            }
        } else {
#pragma unroll
            for (int c8 = 0; c8 < 8; c8++){
                int c = rg*8 + c8;
                const float* xc = xin + (size_t)c*T_LEN;
                int tbase = tb + tq;
                __nv_bfloat16* rowp = sXs + (c*3)*136 + tq;
#pragma unroll
                for (int k = 0; k < 3; k++){
                    int t = tbase + (k-1)*dil;
                    float f0 = (t   >= 0 && t   < T_LEN) ? xc[t]   : 0.f;
                    float f1 = (t+1 >= 0 && t+1 < T_LEN) ? xc[t+1] : 0.f;
                    *(__nv_bfloat162*)(rowp + k*136) = __floats2bfloat162_rn(f0, f1);
                }
            }
        }
    }
    __syncthreads();

    int w = tid >> 5, l = tid & 31;
    int m0 = w*16;
    uint32_t sb32 = smem_u32(smc);

    uint32_t aAddr = sb32 + (uint32_t)(((8*((l>>4)&1) + (l&7))*136 + m0 + 8*((l>>3)&1))*2);
    uint32_t brow = ((l>>4)&1)*8 + (l&7);
    uint32_t bkb  = ((l>>3)&1)*16;
    uint32_t baA = sb32 + 26112u + brow*208 + bkb;
    uint32_t baB = sb32 + 32768u + brow*208 + bkb;
    uint32_t baD = sb32 + 39424u + brow*80  + bkb;

    float aa[4][4], ab[4][4];
#pragma unroll
    for (int j = 0; j < 4; j++)
#pragma unroll
        for (int q = 0; q < 4; q++){ aa[j][q] = 0.f; ab[j][q] = 0.f; }

#pragma unroll
    for (int kk = 0; kk < 6; kk++){
        uint32_t af[4];
        ldsm4t(af[0],af[1],af[2],af[3], aAddr + kk*16*272);
        uint32_t bfa[4][2], bfb[4][2];
#pragma unroll
        for (int j = 0; j < 2; j++){
            ldsm4(bfa[2*j][0],bfa[2*j][1],bfa[2*j+1][0],bfa[2*j+1][1], baA + j*16*208 + kk*32);
            ldsm4(bfb[2*j][0],bfb[2*j][1],bfb[2*j+1][0],bfb[2*j+1][1], baB + j*16*208 + kk*32);
        }
#pragma unroll
        for (int j = 0; j < 4; j++){
            mma16816(aa[j], af, bfa[j]);
            mma16816(ab[j], af, bfb[j]);
        }
    }

    // activation (MUFU.TANH): g = tanh(a+bt)*sigmoid(b+bs)
    int ti2 = 2*(l&3);
    long trow = (long)tb + m0 + (l>>2);
    uint32_t ga[2][4];
#pragma unroll
    for (int j = 0; j < 4; j++){
        int o = 8*j + ti2;
        float bt0 = sbt[o], bt1 = sbt[o+1];
        float bs0 = sbs[o], bs1 = sbs[o+1];
        float gv[4];
#pragma unroll
        for (int q = 0; q < 4; q++){
            float av = aa[j][q] + ((q&1) ? bt1 : bt0);
            float bv = ab[j][q] + ((q&1) ? bs1 : bs0);
            float th = tanh_ap(av);
            float sg = fmaf(0.5f, tanh_ap(0.5f*bv), 0.5f);
            gv[q] = th*sg;
        }
        __nv_bfloat162 p0 = __floats2bfloat162_rn(gv[0], gv[1]);
        __nv_bfloat162 p1 = __floats2bfloat162_rn(gv[2], gv[3]);
        *(uint32_t*)(g_Gt + (size_t)trow*KPAD     + layer*32 + o) = *(uint32_t*)&p0;
        *(uint32_t*)(g_Gt + (size_t)(trow+8)*KPAD + layer*32 + o) = *(uint32_t*)&p1;
        ga[j>>1][(j&1)*2 + 0] = *(uint32_t*)&p0;
        ga[j>>1][(j&1)*2 + 1] = *(uint32_t*)&p1;
    }

    // dense: xout = g @ Wd^T + bd + xin
    float da[4][4];
#pragma unroll
    for (int j = 0; j < 4; j++)
#pragma unroll
        for (int q = 0; q < 4; q++) da[j][q] = 0.f;
#pragma unroll
    for (int kt = 0; kt < 2; kt++){
        uint32_t bfd[4][2];
#pragma unroll
        for (int j = 0; j < 2; j++)
            ldsm4(bfd[2*j][0],bfd[2*j][1],bfd[2*j+1][0],bfd[2*j+1][1], baD + j*16*80 + kt*32);
#pragma unroll
        for (int j = 0; j < 4; j++) mma16816(da[j], ga[kt], bfd[j]);
    }
#pragma unroll
    for (int j = 0; j < 4; j++){
        int o = 8*j + ti2;
        float b0 = sbd[o], b1 = sbd[o+1];
        size_t i00 = (size_t)o*T_LEN + trow;
        size_t i10 = (size_t)(o+1)*T_LEN + trow;
        xout[i00]     = da[j][0] + b0 + xin[i00];
        xout[i10]     = da[j][1] + b1 + xin[i10];
        xout[i00 + 8] = da[j][2] + b0 + xin[i00 + 8];
        xout[i10 + 8] = da[j][3] + b1 + xin[i10 + 8];
    }
}

// ---------------- HMMA GEMM2 (cp.async double-buffered) ----------------
// buffers: A0@0 B0@16384 A1@32768 B1@49152
#define G2_SMEM 65536
__global__ void __launch_bounds__(256) k_hmma2(){
    extern __shared__ char smc[];
    __shared__ float sc0[128];
    uint32_t sbase = smem_u32(smc);
    int tid = threadIdx.x, l = tid & 31, w = tid >> 5;
    int t0 = blockIdx.x*128, s0 = blockIdx.y*128;
    if (tid < 128) sc0[tid] = g_c0[s0 + tid];
    int wm0 = (w & 3)*32, wn0 = (w >> 2)*64;
    float acc[2][8][4];
#pragma unroll
    for (int i = 0; i < 2; i++)
#pragma unroll
        for (int n = 0; n < 8; n++)
#pragma unroll
            for (int q = 0; q < 4; q++) acc[i][n][q] = 0.f;

    const __nv_bfloat16* Abase = g_Gt   + (size_t)t0*KPAD;
    const __nv_bfloat16* Bbase = g_Wallb + (size_t)s0*KPAD;
    int row_ = tid >> 3, kq_ = tid & 7;
    uint32_t so_[4];
#pragma unroll
    for (int u = 0; u < 4; u++) so_[u] = SW128((row_ + u*32)*128 + kq_*16);

    auto issue = [&](int c){
        uint32_t off = (uint32_t)(c & 1)*32768u;
#pragma unroll
        for (int u = 0; u < 4; u++){
            int row = row_ + u*32;
            CPA16(sbase + off + so_[u],         Abase + (size_t)row*KPAD + c*64 + kq_*8);
            CPA16(sbase + off + 16384u + so_[u], Bbase + (size_t)row*KPAD + c*64 + kq_*8);
        }
        CPCG();
    };

    int arow = ((l>>3)&1)*8 + (l&7);
    int akb  = (l>>4)*16;
    int brow = ((l>>4)&1)*8 + (l&7);
    int bkb  = ((l>>3)&1)*16;

    issue(0);
    for (int c = 0; c < 14; c++){
        if (c < 13){ issue(c+1); CPWG(1); } else { CPWG(0); }
        __syncthreads();
        uint32_t mb = sbase + (uint32_t)(c & 1)*32768u;
#pragma unroll
        for (int ks = 0; ks < 4; ks++){
            uint32_t af[2][4], bf[8][2];
#pragma unroll
            for (int i = 0; i < 2; i++)
                ldsm4(af[i][0],af[i][1],af[i][2],af[i][3],
                      mb + SW128((wm0+i*16+arow)*128 + ks*32 + akb));
#pragma unroll
            for (int j = 0; j < 4; j++)
                ldsm4(bf[2*j][0],bf[2*j][1],bf[2*j+1][0],bf[2*j+1][1],
                      mb + 16384u + SW128((wn0+j*16+brow)*128 + ks*32 + bkb));
#pragma unroll
            for (int i = 0; i < 2; i++)
#pragma unroll
                for (int n = 0; n < 8; n++) mma16816(acc[i][n], af[i], bf[n]);
        }
        __syncthreads();
    }
    __nv_bfloat16* cs = (__nv_bfloat16*)smc;
#pragma unroll
    for (int i = 0; i < 2; i++){
        int r = wm0 + i*16 + (l>>2);
#pragma unroll
        for (int n = 0; n < 8; n++){
            int c = wn0 + n*8 + (l&3)*2;
            float b0 = sc0[c], b1 = sc0[c+1];
            *(__nv_bfloat162*)(cs + r*136 + c) =
                __floats2bfloat162_rn(fmaxf(acc[i][n][0]+b0,0.f), fmaxf(acc[i][n][1]+b1,0.f));
            *(__nv_bfloat162*)(cs + (r+8)*136 + c) =
                __floats2bfloat162_rn(fmaxf(acc[i][n][2]+b0,0.f), fmaxf(acc[i][n][3]+b1,0.f));
        }
    }
    __syncthreads();
#pragma unroll
    for (int u = 0; u < 8; u++){
        int idx = tid + u*256; int r = idx >> 4, c8 = idx & 15;
        *(uint4*)(g_ht + (size_t)(t0+r)*SD + s0 + c8*8) = *(const uint4*)(cs + r*136 + c8*8);
    }
}

// ---------------- HMMA GEMM3 + fused log_softmax (cp.async) ----------------
// buffers: A0@0(8K) B0@8192(32K) A1@40960 B1@49152 ; epi cs f32 [64][265]
#define G3_SMEM 81920
__global__ void __launch_bounds__(256) k_hmma3(const float* __restrict__ bp2,
                                               float* __restrict__ out){
    extern __shared__ char smc[];
    __shared__ float sBias[256], sM[256], sS[256], sLZ[64];
    uint32_t sbase = smem_u32(smc);
    int tid = threadIdx.x, l = tid & 31, w = tid >> 5;
    int t0 = blockIdx.x*64;
    sBias[tid] = bp2[tid];
    int tm0 = (w & 3)*16, nh = w >> 2;
    float acc[16][4];
#pragma unroll
    for (int n = 0; n < 16; n++)
#pragma unroll
        for (int q = 0; q < 4; q++) acc[n][q] = 0.f;

    int row_ = tid >> 3, kq_ = tid & 7;
    auto issue = [&](int c){
        uint32_t off = (uint32_t)(c & 1)*40960u;
#pragma unroll
        for (int u = 0; u < 2; u++){
            int row = row_ + u*32;
            CPA16(sbase + off + SW128(row*128 + kq_*16),
                  g_ht + (size_t)(t0+row)*SD + c*64 + kq_*8);
        }
#pragma unroll
        for (int u = 0; u < 8; u++){
            int row = row_ + u*32;
            CPA16(sbase + off + 8192u + SW128(row*128 + kq_*16),
                  g_Wp2b + (size_t)row*SD + c*64 + kq_*8);
        }
        CPCG();
    };

    int arow = ((l>>3)&1)*8 + (l&7);
    int akb  = (l>>4)*16;
    int brow = ((l>>4)&1)*8 + (l&7);
    int bkb  = ((l>>3)&1)*16;

    issue(0);
    for (int c = 0; c < 8; c++){
        if (c < 7){ issue(c+1); CPWG(1); } else { CPWG(0); }
        __syncthreads();
        uint32_t mb = sbase + (uint32_t)(c & 1)*40960u;
#pragma unroll
        for (int ks = 0; ks < 4; ks++){
            uint32_t af[4], bf[16][2];
            ldsm4(af[0],af[1],af[2],af[3],
                  mb + SW128((tm0+arow)*128 + ks*32 + akb));
#pragma unroll
            for (int j = 0; j < 8; j++)
                ldsm4(bf[2*j][0],bf[2*j][1],bf[2*j+1][0],bf[2*j+1][1],
                      mb + 8192u + SW128((nh*128+j*16+brow)*128 + ks*32 + bkb));
#pragma unroll
            for (int n = 0; n < 16; n++) mma16816(acc[n], af, bf[n]);
        }
        __syncthreads();
    }
    float* cs = (float*)smc;
    {
        int r = tm0 + (l>>2);
#pragma unroll
        for (int n = 0; n < 16; n++){
            int q = nh*128 + n*8 + (l&3)*2;
            cs[r*265 + q]       = acc[n][0] + sBias[q];
            cs[r*265 + q + 1]   = acc[n][1] + sBias[q+1];
            cs[(r+8)*265 + q]   = acc[n][2] + sBias[q];
            cs[(r+8)*265 + q+1] = acc[n][3] + sBias[q+1];
        }
    }
    __syncthreads();
    int tt = tid & 63, qg = tid >> 6;
    float m = -1e30f;
#pragma unroll 8
    for (int j = 0; j < 64; j++) m = fmaxf(m, cs[tt*265 + qg*64 + j]);
    float s = 0.f;
#pragma unroll 8
    for (int j = 0; j < 64; j++) s += __expf(cs[tt*265 + qg*64 + j] - m);
    sM[qg*64 + tt] = m; sS[qg*64 + tt] = s;
    __syncthreads();
    if (qg == 0){
        float mm = sM[tt];
#pragma unroll
        for (int g = 1; g < 4; g++) mm = fmaxf(mm, sM[g*64 + tt]);
        float ss = 0.f;
#pragma unroll
        for (int g = 0; g < 4; g++) ss += sS[g*64 + tt]*__expf(sM[g*64 + tt] - mm);
        sLZ[tt] = mm + logf(ss);
    }
    __syncthreads();
    float lz = sLZ[tt];
#pragma unroll 8
    for (int j = 0; j < 64; j++){
        int q = qg*64 + j;
        out[(size_t)q*T_LEN + t0 + tt] = cs[tt*265 + q] - lz;
    }
}

// ---------------- launch ----------------
extern "C" void kernel_launch(void* const* d_in, const int* in_sizes, int n_in,
                              void* d_out, int out_size){
    const float* x     = (const float*)d_in[0];
    const float* Wc    = (const float*)d_in[1];
    const float* bc    = (const float*)d_in[2];
    const float* Wt    = (const float*)d_in[3];
    const float* bt    = (const float*)d_in[4];
    const float* Ws    = (const float*)d_in[5];
    const float* bs    = (const float*)d_in[6];
    const float* Wskip = (const float*)d_in[7];
    const float* bskip = (const float*)d_in[8];
    const float* Wd    = (const float*)d_in[9];
    const float* bd    = (const float*)d_in[10];
    const float* Wp1   = (const float*)d_in[11];
    const float* bp1   = (const float*)d_in[12];
    const float* Wp2   = (const float*)d_in[13];
    const float* bp2   = (const float*)d_in[14];
    float* out = (float*)d_out;

    static const int DIL[NL] = {1,2,4,8,16,32,64,128,256,
                                1,2,4,8,16,32,64,128,256,
                                1,2,4,8,16,32,64,128,256};

    cudaFuncSetAttribute(k_layer, cudaFuncAttributeMaxDynamicSharedMemorySize, LSMEM);
    cudaFuncSetAttribute(k_hmma2, cudaFuncAttributeMaxDynamicSharedMemorySize, G2_SMEM);
    cudaFuncSetAttribute(k_hmma3, cudaFuncAttributeMaxDynamicSharedMemorySize, G3_SMEM);

    k_cvtW<<<NL, 256>>>(Wt, Ws, Wd);
    k_conv0<<<T_LEN/256, 256>>>(x, Wc, bc);
    for (int i = 0; i < NL; i++)
        k_layer<<<T_LEN/TT, 256, LSMEM>>>(bt, bs, bd, i, DIL[i]);
    k_bsum<<<2, 256>>>(bskip);
    k_c0<<<SD, 128>>>(Wp1, bp1);
    k_fold<<<32, 864>>>(Wp1, Wskip);
    k_cvtWall<<<SD, 256>>>();
    k_cvtWp2<<<QD, 256>>>(Wp2);
    k_padG<<<T_LEN/256, 256>>>();
    k_hmma2<<<dim3(T_LEN/128, SD/128), 256, G2_SMEM>>>();
    k_hmma3<<<T_LEN/64, 256, G3_SMEM>>>(bp2, out);
}